// round 1
// baseline (speedup 1.0000x reference)
#include <cuda_runtime.h>
#include <cuda_bf16.h>
#include <cstdint>

// Problem constants
#define NN 100000           // nodes
#define NR 4                // relations
#define NE 500000           // edges per relation
#define DD 128              // feature dim (in == out)

// Scratch (device globals: allocation-free rule)
__device__ float g_z[(size_t)NR * NN * DD];   // z[r][n][d] = (x @ W_r)[n][d]  (~205 MB)
__device__ float g_deg[NR * NN];
__device__ float g_invdeg[NR * NN];

// ---------------------------------------------------------------------------
// Zero degree buffer
__global__ void k_zero_deg() {
    int i = blockIdx.x * blockDim.x + threadIdx.x;
    if (i < NR * NN) g_deg[i] = 0.0f;
}

// Degree count: one thread per (r, e)
__global__ void k_deg(const int* __restrict__ dst_idx) {
    int i = blockIdx.x * blockDim.x + threadIdx.x;
    if (i >= NR * NE) return;
    int r = i / NE;
    int dst = dst_idx[i];
    atomicAdd(&g_deg[r * NN + dst], 1.0f);
}

__global__ void k_invdeg() {
    int i = blockIdx.x * blockDim.x + threadIdx.x;
    if (i < NR * NN) g_invdeg[i] = 1.0f / fmaxf(g_deg[i], 1.0f);
}

// ---------------------------------------------------------------------------
// GEMM: z[r] = x @ W[r].  M=100000, N=128 (per relation), K=128. fp32 FFMA.
// Block tile: 64 nodes x 128 cols (one relation). 256 threads, 8x4 per thread.
// Dynamic smem: As[64][132] + Bs[128][128]  (~97 KB)
#define GEMM_BM 64
#define AS_LD 132
__global__ __launch_bounds__(256) void k_gemm(const float* __restrict__ x,
                                              const float* __restrict__ W) {
    extern __shared__ float smem[];
    float* As = smem;                 // [64][132]
    float* Bs = smem + GEMM_BM * AS_LD; // [128][128]

    const int r  = blockIdx.y;
    const int m0 = blockIdx.x * GEMM_BM;
    const int tid = threadIdx.x;

    // Load W[r] (128x128) into Bs: 4096 float4, 16 per thread, coalesced.
    {
        const float4* Wv = (const float4*)(W + (size_t)r * DD * DD);
        float4* Bv = (float4*)Bs;
#pragma unroll
        for (int i = 0; i < 16; i++) Bv[i * 256 + tid] = Wv[i * 256 + tid];
    }
    // Load x tile (64x128) into As (padded ld=132): 2048 float4, 8 per thread.
    {
#pragma unroll
        for (int i = 0; i < 8; i++) {
            int f  = i * 256 + tid;     // 0..2047
            int n  = f >> 5;            // 32 float4 per row
            int k4 = f & 31;
            float4 v = make_float4(0.f, 0.f, 0.f, 0.f);
            if (m0 + n < NN) v = ((const float4*)(x + (size_t)(m0 + n) * DD))[k4];
            float* d = As + n * AS_LD + k4 * 4;
            d[0] = v.x; d[1] = v.y; d[2] = v.z; d[3] = v.w;
        }
    }
    __syncthreads();

    const int tx = tid & 31;   // output cols tx*4 .. tx*4+3
    const int ty = tid >> 5;   // nodes ty*8 .. ty*8+7

    float acc[8][4];
#pragma unroll
    for (int i = 0; i < 8; i++)
#pragma unroll
        for (int j = 0; j < 4; j++) acc[i][j] = 0.0f;

#pragma unroll 8
    for (int k = 0; k < DD; k++) {
        float4 b = ((const float4*)(Bs + k * DD))[tx];
#pragma unroll
        for (int i = 0; i < 8; i++) {
            float a = As[(ty * 8 + i) * AS_LD + k];   // warp-broadcast LDS
            acc[i][0] = fmaf(a, b.x, acc[i][0]);
            acc[i][1] = fmaf(a, b.y, acc[i][1]);
            acc[i][2] = fmaf(a, b.z, acc[i][2]);
            acc[i][3] = fmaf(a, b.w, acc[i][3]);
        }
    }

    float* zr = g_z + (size_t)r * NN * DD;
#pragma unroll
    for (int i = 0; i < 8; i++) {
        int n = m0 + ty * 8 + i;
        if (n < NN) {
            float4 v = make_float4(acc[i][0], acc[i][1], acc[i][2], acc[i][3]);
            ((float4*)(zr + (size_t)n * DD))[tx] = v;
        }
    }
}

// ---------------------------------------------------------------------------
// Scatter: one warp per (r, e). Gather z[r][src] (512B), scale by 1/deg[r][dst],
// red.add.v4.f32 into out[dst]. Relation-major ordering -> L2-resident working set.
__global__ __launch_bounds__(256) void k_scatter(const int* __restrict__ src_idx,
                                                 const int* __restrict__ dst_idx,
                                                 float* __restrict__ out) {
    unsigned gw = blockIdx.x * (blockDim.x >> 5) + (threadIdx.x >> 5);
    int lane = threadIdx.x & 31;
    if (gw >= (unsigned)(NR * NE)) return;
    int r = gw / NE;                 // relation (edges laid out [r][e], gw == r*NE+e)
    int src = src_idx[gw];           // uniform per warp -> single L1 request
    int dst = dst_idx[gw];
    float inv = g_invdeg[r * NN + dst];

    const float4 v = ((const float4*)(g_z + ((size_t)r * NN + src) * DD))[lane];
    float4 s = make_float4(v.x * inv, v.y * inv, v.z * inv, v.w * inv);
    float* p = out + (size_t)dst * DD + lane * 4;
    asm volatile("red.global.add.v4.f32 [%0], {%1,%2,%3,%4};"
                 :: "l"(p), "f"(s.x), "f"(s.y), "f"(s.z), "f"(s.w)
                 : "memory");
}

// ---------------------------------------------------------------------------
// Epilogue: out = relu(out + sum_r b[r])
__global__ void k_relu_bias(float* __restrict__ out, const float* __restrict__ b) {
    __shared__ float bs[DD];
    if (threadIdx.x < DD) {
        float s = b[threadIdx.x] + b[DD + threadIdx.x] +
                  b[2 * DD + threadIdx.x] + b[3 * DD + threadIdx.x];
        bs[threadIdx.x] = s;
    }
    __syncthreads();
    size_t i4 = (size_t)blockIdx.x * blockDim.x + threadIdx.x;  // float4 index
    size_t total4 = (size_t)NN * DD / 4;
    if (i4 >= total4) return;
    int col = (int)((i4 * 4) & (DD - 1));
    float4* p = (float4*)out + i4;
    float4 v = *p;
    v.x = fmaxf(v.x + bs[col + 0], 0.f);
    v.y = fmaxf(v.y + bs[col + 1], 0.f);
    v.z = fmaxf(v.z + bs[col + 2], 0.f);
    v.w = fmaxf(v.w + bs[col + 3], 0.f);
    *p = v;
}

// ---------------------------------------------------------------------------
extern "C" void kernel_launch(void* const* d_in, const int* in_sizes, int n_in,
                              void* d_out, int out_size) {
    const float* x = (const float*)d_in[0];      // [100000,128]
    const float* W = (const float*)d_in[1];      // [4,128,128]
    const float* b = (const float*)d_in[2];      // [4,128]
    const int* src_idx = (const int*)d_in[3];    // [4,500000]
    const int* dst_idx = (const int*)d_in[4];    // [4,500000]
    float* out = (float*)d_out;                  // [100000,128]

    static const size_t gemm_smem = (GEMM_BM * AS_LD + DD * DD) * sizeof(float);
    cudaFuncSetAttribute(k_gemm, cudaFuncAttributeMaxDynamicSharedMemorySize,
                         (int)gemm_smem);

    // Zero accumulator (d_out is poisoned) and degree buffer.
    cudaMemsetAsync(out, 0, (size_t)NN * DD * sizeof(float));
    k_zero_deg<<<(NR * NN + 255) / 256, 256>>>();

    // Degrees -> inverse degrees
    k_deg<<<(NR * NE + 255) / 256, 256>>>(dst_idx);
    k_invdeg<<<(NR * NN + 255) / 256, 256>>>();

    // z[r] = x @ W[r]
    dim3 ggrid((NN + GEMM_BM - 1) / GEMM_BM, NR);
    k_gemm<<<ggrid, 256, gemm_smem>>>(x, W);

    // Scatter-accumulate into out (one warp per edge)
    int nwarps = NR * NE;                        // 2,000,000
    int sblocks = (nwarps + 7) / 8;              // 8 warps per block
    k_scatter<<<sblocks, 256>>>(src_idx, dst_idx, out);

    // Bias + ReLU
    size_t total4 = (size_t)NN * DD / 4;
    k_relu_bias<<<(int)((total4 + 255) / 256), 256>>>(out, b);
}

// round 9
// speedup vs baseline: 1.2207x; 1.2207x over previous
#include <cuda_runtime.h>
#include <cuda_bf16.h>
#include <cstdint>

// Problem constants
#define NN 100000           // nodes
#define NR 4                // relations
#define NE 500000           // edges per relation
#define DD 128              // feature dim (in == out)
#define PAD 32              // max edges per (relation, dst) bucket in padded CSR
#define OVF_CAP 2048        // fallback list capacity for bucket overflow

// Scratch (device globals: allocation-free rule)
__device__ float g_z[(size_t)NR * NN * DD];      // z[r][n][d] = (x @ W_r)[n][d]
__device__ int   g_cnt[NR * NN];                 // per-(r,dst) edge counts (== degree)
__device__ int   g_slot[(size_t)NR * NN * PAD];  // padded CSR: src indices
__device__ int   g_ovf[OVF_CAP];                 // overflow edge ids (r*NE+e)
__device__ int   g_ovf_n;

// ---------------------------------------------------------------------------
// f32x2 packed helpers (base sm_10x ISA; ptxas never auto-fuses these)
__device__ __forceinline__ uint64_t pack2(float lo, float hi) {
    uint64_t d;
    asm("mov.b64 %0, {%1, %2};" : "=l"(d) : "f"(lo), "f"(hi));
    return d;
}
__device__ __forceinline__ uint64_t pack_rep(float v) {
    uint64_t d;
    asm("mov.b64 %0, {%1, %1};" : "=l"(d) : "f"(v));
    return d;
}
__device__ __forceinline__ void unpack2(float& lo, float& hi, uint64_t v) {
    asm("mov.b64 {%0, %1}, %2;" : "=f"(lo), "=f"(hi) : "l"(v));
}
__device__ __forceinline__ void ffma2(uint64_t& d, uint64_t a, uint64_t b) {
    asm("fma.rn.f32x2 %0, %1, %2, %3;" : "=l"(d) : "l"(a), "l"(b), "l"(d));
}

// ---------------------------------------------------------------------------
__global__ void k_zero_cnt() {
    int i = blockIdx.x * blockDim.x + threadIdx.x;
    if (i < NR * NN) g_cnt[i] = 0;
    if (i == 0) g_ovf_n = 0;
}

// Build padded bucket-CSR: slot[r][dst][c] = src. Overflow -> fallback list.
__global__ void k_fill(const int* __restrict__ src_idx,
                       const int* __restrict__ dst_idx) {
    int i = blockIdx.x * blockDim.x + threadIdx.x;
    if (i >= NR * NE) return;
    int r = i / NE;
    int dst = dst_idx[i];
    int c = atomicAdd(&g_cnt[r * NN + dst], 1);
    if (c < PAD) {
        g_slot[((size_t)r * NN + dst) * PAD + c] = src_idx[i];
    } else {
        int o = atomicAdd(&g_ovf_n, 1);
        if (o < OVF_CAP) g_ovf[o] = i;
    }
}

// ---------------------------------------------------------------------------
// GEMM: for r in 0..3: z[r][m0:m0+64] = x_tile @ W[r].
// A operand stored ROW-PAIR-PACKED in smem: As2[k][p] = {x[m0+2p][k], x[m0+2p+1][k]}
// so fma.rn.f32x2 computes two output rows per instruction.
// 256 threads: warp w owns row-pairs w*4..w*4+3 (rows w*8..w*8+7); lane owns cols lane*4..+3.
#define BM 64
#define AS_STRIDE 33                         // u64 per k-row (33 to break bank conflicts)
#define AS_BYTES (DD * AS_STRIDE * 8)        // 33792
#define SMEM_TOTAL (AS_BYTES + DD * DD * 4)  // + Bs 64KB = 99328

__global__ __launch_bounds__(256) void k_gemm3(const float* __restrict__ x,
                                               const float* __restrict__ W) {
    extern __shared__ char smem[];
    uint64_t* As2 = (uint64_t*)smem;
    float* Bs = (float*)(smem + AS_BYTES);

    const int tid = threadIdx.x;
    const int wid = tid >> 5, lane = tid & 31;
    const int m0 = blockIdx.x * BM;

    // ---- Load x tile (64 rows x 128 k), pack row pairs, transpose into As2.
#pragma unroll
    for (int pass = 0; pass < 4; pass++) {
        int idx = pass * 256 + tid;
        int p = idx >> 5;
        int k4 = idx & 31;
        int r0 = m0 + 2 * p;
        float4 v0 = make_float4(0.f, 0.f, 0.f, 0.f), v1 = v0;
        if (r0 < NN)     v0 = ((const float4*)(x + (size_t)r0 * DD))[k4];
        if (r0 + 1 < NN) v1 = ((const float4*)(x + (size_t)(r0 + 1) * DD))[k4];
        As2[(k4 * 4 + 0) * AS_STRIDE + p] = pack2(v0.x, v1.x);
        As2[(k4 * 4 + 1) * AS_STRIDE + p] = pack2(v0.y, v1.y);
        As2[(k4 * 4 + 2) * AS_STRIDE + p] = pack2(v0.z, v1.z);
        As2[(k4 * 4 + 3) * AS_STRIDE + p] = pack2(v0.w, v1.w);
    }

    for (int r = 0; r < NR; r++) {
        // ---- Load W[r] (128x128 fp32, row-major [k][n]) into Bs, coalesced.
        {
            const float4* Wv = (const float4*)(W + (size_t)r * DD * DD);
            float4* Bv = (float4*)Bs;
#pragma unroll
            for (int i = 0; i < 16; i++) Bv[i * 256 + tid] = Wv[i * 256 + tid];
        }
        __syncthreads();

        uint64_t acc[4][4];
#pragma unroll
        for (int i = 0; i < 4; i++)
#pragma unroll
            for (int j = 0; j < 4; j++) acc[i][j] = 0ull;

        const uint64_t* arow = As2 + wid * 4;
        const float4* brow = (const float4*)Bs + lane;

#pragma unroll 16
        for (int k = 0; k < DD; k++) {
            uint64_t a0 = arow[k * AS_STRIDE + 0];   // broadcast LDS64
            uint64_t a1 = arow[k * AS_STRIDE + 1];
            uint64_t a2 = arow[k * AS_STRIDE + 2];
            uint64_t a3 = arow[k * AS_STRIDE + 3];
            float4 bv = brow[k * 32];                // LDS128, conflict-free
            uint64_t b0 = pack_rep(bv.x), b1 = pack_rep(bv.y);
            uint64_t b2 = pack_rep(bv.z), b3 = pack_rep(bv.w);
            ffma2(acc[0][0], a0, b0); ffma2(acc[0][1], a0, b1);
            ffma2(acc[0][2], a0, b2); ffma2(acc[0][3], a0, b3);
            ffma2(acc[1][0], a1, b0); ffma2(acc[1][1], a1, b1);
            ffma2(acc[1][2], a1, b2); ffma2(acc[1][3], a1, b3);
            ffma2(acc[2][0], a2, b0); ffma2(acc[2][1], a2, b1);
            ffma2(acc[2][2], a2, b2); ffma2(acc[2][3], a2, b3);
            ffma2(acc[3][0], a3, b0); ffma2(acc[3][1], a3, b1);
            ffma2(acc[3][2], a3, b2); ffma2(acc[3][3], a3, b3);
        }
        __syncthreads();

        float* zr = g_z + (size_t)r * NN * DD;
#pragma unroll
        for (int ip = 0; ip < 4; ip++) {
            int re = m0 + wid * 8 + ip * 2;
            float4 lo, hi;
            unpack2(lo.x, hi.x, acc[ip][0]);
            unpack2(lo.y, hi.y, acc[ip][1]);
            unpack2(lo.z, hi.z, acc[ip][2]);
            unpack2(lo.w, hi.w, acc[ip][3]);
            if (re < NN)     ((float4*)(zr + (size_t)re * DD))[lane] = lo;
            if (re + 1 < NN) ((float4*)(zr + (size_t)(re + 1) * DD))[lane] = hi;
        }
    }
}

// ---------------------------------------------------------------------------
// Gather-scatter, de-atomicized: one warp per dst node. For each relation,
// accumulate bucket edges' z rows in registers, scale by 1/deg, sum over
// relations, single plain STG per output row. No atomics, no memset needed.
__global__ __launch_bounds__(256) void k_scatter2(float* __restrict__ out) {
    int gw = blockIdx.x * (blockDim.x >> 5) + (threadIdx.x >> 5);   // dst node
    int lane = threadIdx.x & 31;
    if (gw >= NN) return;

    float4 tot = make_float4(0.f, 0.f, 0.f, 0.f);
#pragma unroll
    for (int r = 0; r < NR; r++) {
        int cnt = g_cnt[r * NN + gw];                 // warp-uniform broadcast
        int n = min(cnt, PAD);
        const int* sl = g_slot + ((size_t)r * NN + gw) * PAD;
        float4 acc = make_float4(0.f, 0.f, 0.f, 0.f);
        for (int j = 0; j < n; j++) {
            int src = sl[j];                          // warp-uniform broadcast
            float4 v = ((const float4*)(g_z + ((size_t)r * NN + src) * DD))[lane];
            acc.x += v.x; acc.y += v.y; acc.z += v.z; acc.w += v.w;
        }
        float inv = 1.0f / (float)max(cnt, 1);
        tot.x += acc.x * inv; tot.y += acc.y * inv;
        tot.z += acc.z * inv; tot.w += acc.w * inv;
    }
    ((float4*)(out + (size_t)gw * DD))[lane] = tot;
}

// Overflow fallback: one warp per overflow edge (rarely any). red.add into out.
__global__ __launch_bounds__(256) void k_scatter_ovf2(const int* __restrict__ src_idx,
                                                      const int* __restrict__ dst_idx,
                                                      float* __restrict__ out) {
    int w = blockIdx.x * (blockDim.x >> 5) + (threadIdx.x >> 5);
    int lane = threadIdx.x & 31;
    int n = min(g_ovf_n, OVF_CAP);
    if (w >= n) return;
    int i = g_ovf[w];                  // edge id = r*NE + e
    int r = i / NE;
    int src = src_idx[i];
    int dst = dst_idx[i];
    float inv = 1.0f / (float)max(g_cnt[r * NN + dst], 1);
    const float4 v = ((const float4*)(g_z + ((size_t)r * NN + src) * DD))[lane];
    float4 s = make_float4(v.x * inv, v.y * inv, v.z * inv, v.w * inv);
    float* p = out + (size_t)dst * DD + lane * 4;
    asm volatile("red.global.add.v4.f32 [%0], {%1,%2,%3,%4};"
                 :: "l"(p), "f"(s.x), "f"(s.y), "f"(s.z), "f"(s.w)
                 : "memory");
}

// ---------------------------------------------------------------------------
__global__ void k_relu_bias(float* __restrict__ out, const float* __restrict__ b) {
    __shared__ float bs[DD];
    if (threadIdx.x < DD) {
        bs[threadIdx.x] = b[threadIdx.x] + b[DD + threadIdx.x] +
                          b[2 * DD + threadIdx.x] + b[3 * DD + threadIdx.x];
    }
    __syncthreads();
    size_t i4 = (size_t)blockIdx.x * blockDim.x + threadIdx.x;
    size_t total4 = (size_t)NN * DD / 4;
    if (i4 >= total4) return;
    int col = (int)((i4 * 4) & (DD - 1));
    float4* p = (float4*)out + i4;
    float4 v = *p;
    v.x = fmaxf(v.x + bs[col + 0], 0.f);
    v.y = fmaxf(v.y + bs[col + 1], 0.f);
    v.z = fmaxf(v.z + bs[col + 2], 0.f);
    v.w = fmaxf(v.w + bs[col + 3], 0.f);
    *p = v;
}

// ---------------------------------------------------------------------------
extern "C" void kernel_launch(void* const* d_in, const int* in_sizes, int n_in,
                              void* d_out, int out_size) {
    const float* x = (const float*)d_in[0];      // [100000,128]
    const float* W = (const float*)d_in[1];      // [4,128,128]
    const float* b = (const float*)d_in[2];      // [4,128]
    const int* src_idx = (const int*)d_in[3];    // [4,500000]
    const int* dst_idx = (const int*)d_in[4];    // [4,500000]
    float* out = (float*)d_out;                  // [100000,128]

    cudaFuncSetAttribute(k_gemm3, cudaFuncAttributeMaxDynamicSharedMemorySize,
                         SMEM_TOTAL);

    // Build padded bucket-CSR (counts double as degrees).
    k_zero_cnt<<<(NR * NN + 255) / 256, 256>>>();
    k_fill<<<(NR * NE + 255) / 256, 256>>>(src_idx, dst_idx);

    // z[r] = x @ W[r], all relations per block (x tile loaded once)
    int mtiles = (NN + BM - 1) / BM;             // 1563
    k_gemm3<<<mtiles, 256, SMEM_TOTAL>>>(x, W);

    // De-atomicized gather-accumulate: one warp per dst row, plain STG.
    k_scatter2<<<(NN + 7) / 8, 256>>>(out);

    // Rare bucket-overflow edges (usually zero) accumulate atomically.
    k_scatter_ovf2<<<(OVF_CAP / 8 + 1), 256>>>(src_idx, dst_idx, out);

    // Bias + ReLU
    size_t total4 = (size_t)NN * DD / 4;
    k_relu_bias<<<(int)((total4 + 255) / 256), 256>>>(out, b);
}